// round 15
// baseline (speedup 1.0000x reference)
#include <cuda_runtime.h>
#include <cuda_fp16.h>
#include <math.h>

// ---------------------------------------------------------------------------
// DeepSeek V2 MLA attention prefill — fp16 mma.sync m16n8k16 + ldmatrix.
// Dense GEMMs: 128x128x64 CTA tile, 4 warps (2x2 grid, 64x64 warp tiles) —
// halves smem fragment redundancy vs 8-warp layout. 3-stage cp.async,
// 2 CTAs/SM, stream overlap. Attention: 64-row q-tiles, register softmax+P.
// ---------------------------------------------------------------------------

namespace {
constexpr int T_      = 2048;
constexpr int H_      = 32;
constexpr int HIDDEN_ = 5120;
constexpr int QL_     = 1536;
constexpr int KVL_    = 512;
constexpr int DN_     = 128;
constexpr int DR_     = 64;
constexpr int DQK_    = 192;
constexpr int DV_     = 128;
constexpr int CKVP_   = 640;
constexpr int NMERGE_ = QL_ + CKVP_;         // 2176
constexpr float EPS_  = 1e-6f;
constexpr float SC2_  = 0.07216878364870323f * 1.4426950408889634f;

// fp16 dense GEMM smem (halves), tile 128x128x64, 3 stages
constexpr int APAD_H = 72;
constexpr int BPAD_H = 136;
constexpr int ASTG_H = 128 * APAD_H;
constexpr int BSTG_H = 64 * BPAD_H;
constexpr int STG_H  = ASTG_H + BSTG_H;
constexpr int GSMEM_BYTES = 3 * STG_H * 2;   // 107520 B

// fused attention smem (halves): Q 64x200, K 128x200, V 128x136
constexpr int QPAD_B = 200;
constexpr int KPAD_B = 200;
constexpr int VPAD_B = 136;
constexpr int AQ_B   = 64 * QPAD_B;
constexpr int AK_B   = 128 * KPAD_B;
constexpr int AV_B   = 128 * VPAD_B;
constexpr int FUSED_SMEM = (AQ_B + AK_B + AV_B) * 2;   // 111616 B
}

// ------------------------- scratch (static device) -------------------------
__device__ __half g_hidH[(long)T_ * HIDDEN_];
__device__ float  g_qack[(long)T_ * NMERGE_];
__device__ __half g_qa16[(long)T_ * QL_];
__device__ __half g_q16[(long)T_ * H_ * DQK_];
__device__ __half g_cn16[(long)T_ * KVL_];
__device__ __half g_kv16[(long)T_ * H_ * (DN_ + DV_)];
__device__ __half g_kr16[(long)T_ * DR_];
__device__ __half g_ctx16[(long)T_ * H_ * DV_];
__device__ __half g_wqac[(long)HIDDEN_ * NMERGE_];
__device__ __half g_wqb [(long)QL_ * (H_ * DQK_)];
__device__ __half g_wkvb[(long)KVL_ * (H_ * (DN_ + DV_))];
__device__ __half g_wo  [(long)(H_ * DV_) * HIDDEN_];

// ------------------------------ helpers ------------------------------------
__device__ __forceinline__ void mma_f16(float* d, const unsigned* a, const unsigned* b) {
    asm volatile(
        "mma.sync.aligned.m16n8k16.row.col.f32.f16.f16.f32 "
        "{%0,%1,%2,%3}, {%4,%5,%6,%7}, {%8,%9}, {%0,%1,%2,%3};"
        : "+f"(d[0]), "+f"(d[1]), "+f"(d[2]), "+f"(d[3])
        : "r"(a[0]), "r"(a[1]), "r"(a[2]), "r"(a[3]),
          "r"(b[0]), "r"(b[1]));
}

__device__ __forceinline__ void ldsm_x4(unsigned* r, unsigned addr) {
    asm volatile("ldmatrix.sync.aligned.m8n8.x4.shared.b16 {%0,%1,%2,%3}, [%4];"
                 : "=r"(r[0]), "=r"(r[1]), "=r"(r[2]), "=r"(r[3]) : "r"(addr));
}
__device__ __forceinline__ void ldsm_x4t(unsigned* r, unsigned addr) {
    asm volatile("ldmatrix.sync.aligned.m8n8.x4.trans.shared.b16 {%0,%1,%2,%3}, [%4];"
                 : "=r"(r[0]), "=r"(r[1]), "=r"(r[2]), "=r"(r[3]) : "r"(addr));
}

__device__ __forceinline__ unsigned smem_u32(const void* p) {
    return (unsigned)__cvta_generic_to_shared(p);
}
__device__ __forceinline__ void cp16(unsigned dst, const void* src) {
    asm volatile("cp.async.cg.shared.global [%0], [%1], 16;\n" :: "r"(dst), "l"(src));
}
__device__ __forceinline__ unsigned exp2_f16x2(float lo, float hi) {
    unsigned h;
    asm("cvt.rn.f16x2.f32 %0, %1, %2;" : "=r"(h) : "f"(hi), "f"(lo));
    asm("ex2.approx.f16x2 %0, %0;" : "+r"(h));
    return h;
}

// ------------------------------- FP16 GEMM ---------------------------------
// C[M,N] = A @ B. Tile 128x128x64, 4 warps (2x2 grid, 64x64 warp tiles),
// 3-stage cp.async, 2 CTAs/SM. OUT: 0 = float C, 1 = half C.
template<int OUT>
__global__ __launch_bounds__(128, 2)
void hgemm_kernel(const __half* __restrict__ A,
                  const __half* __restrict__ B,
                  void* __restrict__ Cv,
                  int M, int N, int K,
                  int lda, int ldb, int ldc)
{
    constexpr int BK = 64, S = 3;
    const int bx = blockIdx.x, by = blockIdx.y;

    extern __shared__ __half hsm[];

    const int tid  = threadIdx.x;
    const int lane = tid & 31;
    const int warp = tid >> 5;       // 0..3
    const int gid  = lane >> 2;
    const int tig  = lane & 3;
    const int wr   = warp & 1;
    const int wc   = warp >> 1;
    const int rowBase = by * 128, colBase = bx * 128;
    const int wm = wr * 64, wn = wc * 64;

    const int tiles = K / BK;

    auto load_tile = [&](int st, int kt) {
        const int k0 = kt * BK;
        __half* As = hsm + st * STG_H;
        __half* Bs = As + ASTG_H;
        #pragma unroll
        for (int i = 0; i < 8; i++) {        // A: 128 rows x 64 k
            int c = tid + i * 128;
            int r = c >> 3, kc = (c & 7) * 8;
            cp16(smem_u32(As + r * APAD_H + kc),
                 A + (long)(rowBase + r) * lda + k0 + kc);
        }
        #pragma unroll
        for (int i = 0; i < 8; i++) {        // B: 64 rows x 128 n
            int c = tid + i * 128;
            int r = c >> 4, nc = (c & 15) * 8;
            cp16(smem_u32(Bs + r * BPAD_H + nc),
                 B + (long)(k0 + r) * ldb + colBase + nc);
        }
    };

    #pragma unroll
    for (int s = 0; s < S - 1; s++) {
        load_tile(s, s);
        asm volatile("cp.async.commit_group;\n");
    }

    float acc[4][8][4];
    #pragma unroll
    for (int i = 0; i < 4; i++)
        #pragma unroll
        for (int j = 0; j < 8; j++)
            #pragma unroll
            for (int v = 0; v < 4; v++) acc[i][j][v] = 0.0f;

    const int arow = lane & 15;
    const int acol = (lane >> 4) * 8;

    for (int t = 0; t < tiles; t++) {
        asm volatile("cp.async.wait_group %0;\n" :: "n"(S - 2));
        __syncthreads();

        int tn = t + S - 1;
        if (tn < tiles) load_tile(tn % S, tn);
        asm volatile("cp.async.commit_group;\n");

        const __half* Asb = hsm + (t % S) * STG_H;
        const __half* Bsb = Asb + ASTG_H;

        #pragma unroll
        for (int ks = 0; ks < 4; ks++) {
            const int kb = ks * 16;
            unsigned af[4][4];
            #pragma unroll
            for (int mt = 0; mt < 4; mt++)
                ldsm_x4(af[mt],
                        smem_u32(Asb + (wm + mt * 16 + arow) * APAD_H + kb + acol));

            unsigned b0 = smem_u32(Bsb + (kb + arow) * BPAD_H + wn + acol);
            #pragma unroll
            for (int p = 0; p < 4; p++) {
                unsigned bf[4];
                ldsm_x4t(bf, b0 + p * 32);
                #pragma unroll
                for (int mt = 0; mt < 4; mt++) {
                    mma_f16(acc[mt][2 * p    ], af[mt], bf + 0);
                    mma_f16(acc[mt][2 * p + 1], af[mt], bf + 2);
                }
            }
        }
    }

    #pragma unroll
    for (int mt = 0; mt < 4; mt++) {
        #pragma unroll
        for (int nt = 0; nt < 8; nt++) {
            int gc = colBase + wn + nt * 8 + tig * 2;
            #pragma unroll
            for (int half = 0; half < 2; half++) {
                int gr = rowBase + wm + mt * 16 + gid + half * 8;
                float x0 = acc[mt][nt][half * 2];
                float x1 = acc[mt][nt][half * 2 + 1];
                if (OUT == 0) {
                    float* C = (float*)Cv;
                    *reinterpret_cast<float2*>(&C[(long)gr * ldc + gc]) =
                        make_float2(x0, x1);
                } else {
                    __half* C = (__half*)Cv;
                    *reinterpret_cast<__half2*>(&C[(long)gr * ldc + gc]) =
                        __floats2half2_rn(x0, x1);
                }
            }
        }
    }
}

// --------------------- fused flash attention (fp16 mma) --------------------
__global__ __launch_bounds__(128, 2)
void fused_attn_kernel(const __half* __restrict__ q,
                       const __half* __restrict__ kv,
                       const __half* __restrict__ kr,
                       __half* __restrict__ ctx)
{
    extern __shared__ __half hs[];
    __half* Qs = hs;
    __half* Ks = hs + AQ_B;
    __half* Vs = hs + AQ_B + AK_B;

    const int qt = 31 - blockIdx.x;
    const int h  = blockIdx.y;
    const int q0 = qt * 64;
    const int jmax = qt / 2 + 1;

    const int tid  = threadIdx.x;
    const int lane = tid & 31;
    const int warp = tid >> 5;
    const int gid  = lane >> 2;
    const int tig  = lane & 3;
    const int wm   = warp * 16;
    const int KVROW = H_ * (DN_ + DV_);

    const int arow = lane & 15;
    const int acol = (lane >> 4) * 8;
    const int krow_off = ((lane >> 4) << 3) + (lane & 7);
    const int kcol_off = ((lane >> 3) & 1) << 3;

    auto load_K = [&](int j) {
        const long key0 = (long)j * 128;
        #pragma unroll
        for (int i = 0; i < 24; i++) {
            int e = tid + i * 128;
            int r = e / 24;
            int fc = (e % 24) * 8;
            const __half* src = (fc < DN_)
                ? kv + (key0 + r) * (long)KVROW + h * (DN_ + DV_) + fc
                : kr + (key0 + r) * (long)DR_ + (fc - DN_);
            cp16(smem_u32(Ks + r * KPAD_B + fc), src);
        }
    };
    auto load_V = [&](int j) {
        const long key0 = (long)j * 128;
        #pragma unroll
        for (int i = 0; i < 16; i++) {
            int e = tid + i * 128;
            int r = e >> 4;
            int fc = (e & 15) * 8;
            cp16(smem_u32(Vs + r * VPAD_B + fc),
                 kv + (key0 + r) * (long)KVROW + h * (DN_ + DV_) + DN_ + fc);
        }
    };

    const __half* Qbase = q + (long)q0 * (H_ * DQK_) + h * DQK_;
    #pragma unroll
    for (int i = 0; i < 12; i++) {
        int e = tid + i * 128;
        int r = e / 24;
        int fc = (e % 24) * 8;
        cp16(smem_u32(Qs + r * QPAD_B + fc), Qbase + (long)r * (H_ * DQK_) + fc);
    }
    load_K(0);
    asm volatile("cp.async.commit_group;\n");

    float m0 = -1e30f, m1 = -1e30f, l0 = 0.0f, l1 = 0.0f;
    float Oacc[16][4];
    #pragma unroll
    for (int i = 0; i < 16; i++)
        #pragma unroll
        for (int v = 0; v < 4; v++) Oacc[i][v] = 0.0f;

    const int row_g0 = q0 + wm + gid;
    const int row_g1 = row_g0 + 8;

    for (int j = 0; j < jmax; j++) {
        const bool diag = (j == jmax - 1);
        const int key0 = j * 128;

        load_V(j);
        asm volatile("cp.async.commit_group;\n");
        asm volatile("cp.async.wait_group 1;\n");
        __syncthreads();

        float Sacc[16][4];
        #pragma unroll
        for (int i = 0; i < 16; i++)
            #pragma unroll
            for (int v = 0; v < 4; v++) Sacc[i][v] = 0.0f;

        #pragma unroll
        for (int ks = 0; ks < 12; ks++) {
            const int kb = ks * 16;
            unsigned af[4];
            ldsm_x4(af, smem_u32(Qs + (wm + arow) * QPAD_B + kb + acol));
            #pragma unroll
            for (int nt2 = 0; nt2 < 8; nt2++) {
                unsigned bf[4];
                ldsm_x4(bf, smem_u32(Ks + (nt2 * 16 + krow_off) * KPAD_B
                                     + kb + kcol_off));
                mma_f16(Sacc[2 * nt2    ], af, bf + 0);
                mma_f16(Sacc[2 * nt2 + 1], af, bf + 2);
            }
        }
        __syncthreads();

        if (j + 1 < jmax) {
            load_K(j + 1);
            asm volatile("cp.async.commit_group;\n");
        }

        #pragma unroll
        for (int nt = 0; nt < 16; nt++)
            #pragma unroll
            for (int v = 0; v < 4; v++) {
                int key_g = key0 + nt * 8 + tig * 2 + (v & 1);
                int row_g = (v >> 1) ? row_g1 : row_g0;
                float s = Sacc[nt][v] * SC2_;
                if (diag && key_g > row_g) s = -1e30f;
                Sacc[nt][v] = s;
            }

        float mx0 = -1e30f, mx1 = -1e30f;
        #pragma unroll
        for (int nt = 0; nt < 16; nt++) {
            mx0 = fmaxf(mx0, fmaxf(Sacc[nt][0], Sacc[nt][1]));
            mx1 = fmaxf(mx1, fmaxf(Sacc[nt][2], Sacc[nt][3]));
        }
        mx0 = fmaxf(mx0, __shfl_xor_sync(0xffffffffu, mx0, 1));
        mx0 = fmaxf(mx0, __shfl_xor_sync(0xffffffffu, mx0, 2));
        mx1 = fmaxf(mx1, __shfl_xor_sync(0xffffffffu, mx1, 1));
        mx1 = fmaxf(mx1, __shfl_xor_sync(0xffffffffu, mx1, 2));

        float mn0 = fmaxf(m0, mx0), mn1 = fmaxf(m1, mx1);
        float r0 = exp2f(m0 - mn0), r1 = exp2f(m1 - mn1);
        m0 = mn0; m1 = mn1;

        #pragma unroll
        for (int nt = 0; nt < 16; nt++) {
            Oacc[nt][0] *= r0; Oacc[nt][1] *= r0;
            Oacc[nt][2] *= r1; Oacc[nt][3] *= r1;
        }

        unsigned pa[8][4];
        float s0 = 0.0f, s1 = 0.0f;
        #pragma unroll
        for (int c = 0; c < 8; c++) {
            pa[c][0] = exp2_f16x2(Sacc[2 * c][0] - m0, Sacc[2 * c][1] - m0);
            pa[c][1] = exp2_f16x2(Sacc[2 * c][2] - m1, Sacc[2 * c][3] - m1);
            pa[c][2] = exp2_f16x2(Sacc[2 * c + 1][0] - m0, Sacc[2 * c + 1][1] - m0);
            pa[c][3] = exp2_f16x2(Sacc[2 * c + 1][2] - m1, Sacc[2 * c + 1][3] - m1);
            float2 p;
            p = __half22float2(*reinterpret_cast<__half2*>(&pa[c][0])); s0 += p.x + p.y;
            p = __half22float2(*reinterpret_cast<__half2*>(&pa[c][2])); s0 += p.x + p.y;
            p = __half22float2(*reinterpret_cast<__half2*>(&pa[c][1])); s1 += p.x + p.y;
            p = __half22float2(*reinterpret_cast<__half2*>(&pa[c][3])); s1 += p.x + p.y;
        }
        s0 += __shfl_xor_sync(0xffffffffu, s0, 1);
        s0 += __shfl_xor_sync(0xffffffffu, s0, 2);
        s1 += __shfl_xor_sync(0xffffffffu, s1, 1);
        s1 += __shfl_xor_sync(0xffffffffu, s1, 2);
        l0 = l0 * r0 + s0;
        l1 = l1 * r1 + s1;

        asm volatile("cp.async.wait_group %0;\n" :: "n"(1) : "memory");
        if (j + 1 >= jmax)
            asm volatile("cp.async.wait_group 0;\n" ::: "memory");
        __syncthreads();

        #pragma unroll
        for (int c = 0; c < 8; c++) {
            const int kc = c * 16;
            unsigned vb = smem_u32(Vs + (kc + arow) * VPAD_B + acol);
            #pragma unroll
            for (int p = 0; p < 8; p++) {
                unsigned bf[4];
                ldsm_x4t(bf, vb + p * 32);
                mma_f16(Oacc[2 * p    ], pa[c], bf + 0);
                mma_f16(Oacc[2 * p + 1], pa[c], bf + 2);
            }
        }
        __syncthreads();
    }

    const float inv0 = 1.0f / l0, inv1 = 1.0f / l1;
    #pragma unroll
    for (int nt = 0; nt < 16; nt++) {
        int cl = nt * 8 + tig * 2;
        *reinterpret_cast<__half2*>(
            &ctx[(long)row_g0 * (H_ * DV_) + h * DV_ + cl]) =
            __floats2half2_rn(Oacc[nt][0] * inv0, Oacc[nt][1] * inv0);
        *reinterpret_cast<__half2*>(
            &ctx[(long)row_g1 * (H_ * DV_) + h * DV_ + cl]) =
            __floats2half2_rn(Oacc[nt][2] * inv1, Oacc[nt][3] * inv1);
    }
}

// ------------------------------ prep kernels --------------------------------
__global__ void convert4_kernel(const float* s0, __half* d0, long c0,
                                const float* s1, __half* d1, long c1,
                                const float* s2, __half* d2, long c2,
                                const float* s3, __half* d3, long c3)
{
    long i = (long)blockIdx.x * blockDim.x + threadIdx.x;
    const float* s; __half* d;
    if (i < c0)                { s = s0; d = d0; }
    else if ((i -= c0) < c1)   { s = s1; d = d1; }
    else if ((i -= c1) < c2)   { s = s2; d = d2; }
    else if ((i -= c2) < c3)   { s = s3; d = d3; }
    else return;
    long e = i * 4;
    float4 v = *reinterpret_cast<const float4*>(s + e);
    union { __half2 h[2]; uint2 u; } cv;
    cv.h[0] = __floats2half2_rn(v.x, v.y);
    cv.h[1] = __floats2half2_rn(v.z, v.w);
    *reinterpret_cast<uint2*>(d + e) = cv.u;
}

__global__ void tohalf8_strided(const float* __restrict__ in, int ldin, int Cin,
                                __half* __restrict__ out, int ldout, int chunks)
{
    long idx = (long)blockIdx.x * blockDim.x + threadIdx.x;
    int r  = (int)(idx / chunks);
    int c  = (int)(idx % chunks) * 8;
    union { __half2 h[4]; uint4 u; } cv;
    if (c < Cin) {
        const float* src = in + (long)r * ldin + c;
        float4 a = *reinterpret_cast<const float4*>(src);
        float4 b = *reinterpret_cast<const float4*>(src + 4);
        cv.h[0] = __floats2half2_rn(a.x, a.y);
        cv.h[1] = __floats2half2_rn(a.z, a.w);
        cv.h[2] = __floats2half2_rn(b.x, b.y);
        cv.h[3] = __floats2half2_rn(b.z, b.w);
    } else {
        cv.u = make_uint4(0, 0, 0, 0);
    }
    *reinterpret_cast<uint4*>(out + (long)r * ldout + c) = cv.u;
}

// ------------------------------ RMSNorm (half out) --------------------------
__global__ void rmsnorm_h_kernel(const float* __restrict__ x,
                                 const float* __restrict__ w,
                                 __half* __restrict__ y,
                                 int L, int ldx, int ldy)
{
    const int row = blockIdx.x, tid = threadIdx.x;
    const float* xr = x + (long)row * ldx;
    __half* yr = y + (long)row * ldy;

    __shared__ float red[256];
    float s = 0.0f;
    for (int i = tid; i < L; i += 256) { float v = xr[i]; s += v * v; }
    red[tid] = s; __syncthreads();
    for (int o = 128; o > 0; o >>= 1) {
        if (tid < o) red[tid] += red[tid + o];
        __syncthreads();
    }
    const float scale = rsqrtf(red[0] / (float)L + EPS_);
    for (int i = tid; i < L; i += 256)
        yr[i] = __float2half_rn(xr[i] * scale * w[i]);
}

// -------------------------------- RoPE --------------------------------------
__global__ void rope_q_kernel(__half* __restrict__ q,
                              const float* __restrict__ cosT,
                              const float* __restrict__ sinT)
{
    const int t = blockIdx.x;
    const int w = threadIdx.x >> 5, lane = threadIdx.x & 31;
    const float c = cosT[(long)t * DR_ + lane];
    const float s = sinT[(long)t * DR_ + lane];
    #pragma unroll
    for (int it = 0; it < 4; it++) {
        int h = it * 8 + w;
        __half* p = q + (long)t * (H_ * DQK_) + h * DQK_ + DN_;
        __half2 v = *reinterpret_cast<const __half2*>(p + 2 * lane);
        float lo = __half2float(v.x), hi = __half2float(v.y);
        __syncwarp();
        p[lane]      = __float2half_rn(lo * c - hi * s);
        p[lane + 32] = __float2half_rn(hi * c + lo * s);
    }
}

__global__ void rope_k_kernel(const float* __restrict__ ckv_pe,
                              __half* __restrict__ kr,
                              const float* __restrict__ cosT,
                              const float* __restrict__ sinT, int ld)
{
    const int t = blockIdx.x * 8 + (threadIdx.x >> 5);
    const int lane = threadIdx.x & 31;
    const float c = cosT[(long)t * DR_ + lane];
    const float s = sinT[(long)t * DR_ + lane];
    float2 v = *reinterpret_cast<const float2*>(ckv_pe + (long)t * ld + 2 * lane);
    __half* o = kr + (long)t * DR_;
    o[lane]      = __float2half_rn(v.x * c - v.y * s);
    o[lane + 32] = __float2half_rn(v.y * c + v.x * s);
}

// ------------------------------- launch ------------------------------------
extern "C" void kernel_launch(void* const* d_in, const int* in_sizes, int n_in,
                              void* d_out, int out_size)
{
    const float* hidden = (const float*)d_in[0];
    const float* cosT   = (const float*)d_in[1];
    const float* sinT   = (const float*)d_in[2];
    const float* wq_a   = (const float*)d_in[3];
    const float* q_ln   = (const float*)d_in[4];
    const float* wq_b   = (const float*)d_in[5];
    const float* wkv_a  = (const float*)d_in[6];
    const float* kv_ln  = (const float*)d_in[7];
    const float* wkv_b  = (const float*)d_in[8];
    const float* wo     = (const float*)d_in[9];
    float* out = (float*)d_out;

    static __half *hidH = nullptr, *qa16 = nullptr, *q16 = nullptr,
                  *cn16 = nullptr, *kv16 = nullptr, *kr16 = nullptr,
                  *ctx16 = nullptr, *wqac = nullptr, *wqb = nullptr,
                  *wkvb = nullptr, *woH = nullptr;
    static float *qack = nullptr;
    static cudaStream_t s2 = nullptr;
    static cudaEvent_t evFork, evW, evA, evB;
    if (!qack) {
        cudaGetSymbolAddress((void**)&hidH,  g_hidH);
        cudaGetSymbolAddress((void**)&qack,  g_qack);
        cudaGetSymbolAddress((void**)&qa16,  g_qa16);
        cudaGetSymbolAddress((void**)&q16,   g_q16);
        cudaGetSymbolAddress((void**)&cn16,  g_cn16);
        cudaGetSymbolAddress((void**)&kv16,  g_kv16);
        cudaGetSymbolAddress((void**)&kr16,  g_kr16);
        cudaGetSymbolAddress((void**)&ctx16, g_ctx16);
        cudaGetSymbolAddress((void**)&wqac,  g_wqac);
        cudaGetSymbolAddress((void**)&wqb,   g_wqb);
        cudaGetSymbolAddress((void**)&wkvb,  g_wkvb);
        cudaGetSymbolAddress((void**)&woH,   g_wo);
        cudaFuncSetAttribute(hgemm_kernel<0>,
                             cudaFuncAttributeMaxDynamicSharedMemorySize, GSMEM_BYTES);
        cudaFuncSetAttribute(hgemm_kernel<1>,
                             cudaFuncAttributeMaxDynamicSharedMemorySize, GSMEM_BYTES);
        cudaFuncSetAttribute(fused_attn_kernel,
                             cudaFuncAttributeMaxDynamicSharedMemorySize, FUSED_SMEM);
        cudaStreamCreateWithFlags(&s2, cudaStreamNonBlocking);
        cudaEventCreateWithFlags(&evFork, cudaEventDisableTiming);
        cudaEventCreateWithFlags(&evW,    cudaEventDisableTiming);
        cudaEventCreateWithFlags(&evA,    cudaEventDisableTiming);
        cudaEventCreateWithFlags(&evB,    cudaEventDisableTiming);
    }

    // ---- fork second stream
    cudaEventRecord(evFork, 0);
    cudaStreamWaitEvent(s2, evFork, 0);

    // s2: convert wq_b, wkv_b, wo
    const long c1 = (long)QL_ * (H_ * DQK_) / 4;
    const long c2 = (long)KVL_ * (H_ * (DN_ + DV_)) / 4;
    const long c3 = (long)(H_ * DV_) * HIDDEN_ / 4;
    convert4_kernel<<<(int)((c1 + c2 + c3 + 255) / 256), 256, 0, s2>>>(
        wq_b, wqb, c1, wkv_b, wkvb, c2, wo, woH, c3, nullptr, nullptr, 0);
    cudaEventRecord(evW, s2);

    // s0: hidden + merged A-proj weights, then merged GEMM
    const long c0 = (long)T_ * HIDDEN_ / 4;
    convert4_kernel<<<(int)((c0 + 255) / 256), 256>>>(
        hidden, hidH, c0, nullptr, nullptr, 0, nullptr, nullptr, 0,
        nullptr, nullptr, 0);
    tohalf8_strided<<<(HIDDEN_ * (QL_ / 8)) / 256, 256>>>(
        wq_a, QL_, QL_, wqac, NMERGE_, QL_ / 8);
    tohalf8_strided<<<(HIDDEN_ * (CKVP_ / 8)) / 256, 256>>>(
        wkv_a, KVL_ + DR_, KVL_ + DR_, wqac + QL_, NMERGE_, CKVP_ / 8);

    hgemm_kernel<0><<<dim3(NMERGE_ / 128, 16), 128, GSMEM_BYTES>>>(
        hidH, wqac, qack, T_, NMERGE_, HIDDEN_, HIDDEN_, NMERGE_, NMERGE_);
    cudaEventRecord(evA, 0);

    // kv chain on s2
    cudaStreamWaitEvent(s2, evA, 0);
    rmsnorm_h_kernel<<<T_, 256, 0, s2>>>(qack + QL_, kv_ln, cn16, KVL_, NMERGE_, KVL_);
    hgemm_kernel<1><<<dim3(H_ * (DN_ + DV_) / 128, 16), 128, GSMEM_BYTES, s2>>>(
        cn16, wkvb, kv16, T_, H_ * (DN_ + DV_), KVL_,
        KVL_, H_ * (DN_ + DV_), H_ * (DN_ + DV_));
    rope_k_kernel<<<T_ / 8, 256, 0, s2>>>(qack + QL_ + KVL_, kr16, cosT, sinT, NMERGE_);
    cudaEventRecord(evB, s2);

    // q chain on main stream
    rmsnorm_h_kernel<<<T_, 256>>>(qack, q_ln, qa16, QL_, NMERGE_, QL_);
    cudaStreamWaitEvent(0, evW, 0);
    hgemm_kernel<1><<<dim3(H_ * DQK_ / 128, 16), 128, GSMEM_BYTES>>>(
        qa16, wqb, q16, T_, H_ * DQK_, QL_, QL_, H_ * DQK_, H_ * DQK_);
    rope_q_kernel<<<T_, 256>>>(q16, cosT, sinT);

    // join + attention + out GEMM
    cudaStreamWaitEvent(0, evB, 0);
    fused_attn_kernel<<<dim3(32, H_), 128, FUSED_SMEM>>>(q16, kv16, kr16, ctx16);
    hgemm_kernel<0><<<dim3(HIDDEN_ / 128, 16), 128, GSMEM_BYTES>>>(
        ctx16, woH, out, T_, HIDDEN_, H_ * DV_, H_ * DV_, HIDDEN_, HIDDEN_);
}

// round 16
// speedup vs baseline: 1.0612x; 1.0612x over previous
#include <cuda_runtime.h>
#include <cuda_fp16.h>
#include <math.h>

// ---------------------------------------------------------------------------
// DeepSeek V2 MLA attention prefill — fp16 mma.sync m16n8k16 + ldmatrix.
// Dense GEMMs: 128x128x64 tiles, 8 warps (4Mx2N), 3-stage cp.async, 2 CTAs/SM.
// Attention: 64-row q-tiles, register softmax + register P. Stream overlap;
// A-proj weight converts moved off the critical path (s2).
// ---------------------------------------------------------------------------

namespace {
constexpr int T_      = 2048;
constexpr int H_      = 32;
constexpr int HIDDEN_ = 5120;
constexpr int QL_     = 1536;
constexpr int KVL_    = 512;
constexpr int DN_     = 128;
constexpr int DR_     = 64;
constexpr int DQK_    = 192;
constexpr int DV_     = 128;
constexpr int CKVP_   = 640;
constexpr int NMERGE_ = QL_ + CKVP_;         // 2176
constexpr float EPS_  = 1e-6f;
constexpr float SC2_  = 0.07216878364870323f * 1.4426950408889634f;

// fp16 dense GEMM smem (halves), tile 128x128x64, 3 stages
constexpr int APAD_H = 72;
constexpr int BPAD_H = 136;
constexpr int ASTG_H = 128 * APAD_H;
constexpr int BSTG_H = 64 * BPAD_H;
constexpr int STG_H  = ASTG_H + BSTG_H;
constexpr int GSMEM_BYTES = 3 * STG_H * 2;   // 107520 B

// fused attention smem (halves): Q 64x200, K 128x200, V 128x136
constexpr int QPAD_B = 200;
constexpr int KPAD_B = 200;
constexpr int VPAD_B = 136;
constexpr int AQ_B   = 64 * QPAD_B;
constexpr int AK_B   = 128 * KPAD_B;
constexpr int AV_B   = 128 * VPAD_B;
constexpr int FUSED_SMEM = (AQ_B + AK_B + AV_B) * 2;   // 111616 B
}

// ------------------------- scratch (static device) -------------------------
__device__ __half g_hidH[(long)T_ * HIDDEN_];
__device__ float  g_qack[(long)T_ * NMERGE_];
__device__ __half g_qa16[(long)T_ * QL_];
__device__ __half g_q16[(long)T_ * H_ * DQK_];
__device__ __half g_cn16[(long)T_ * KVL_];
__device__ __half g_kv16[(long)T_ * H_ * (DN_ + DV_)];
__device__ __half g_kr16[(long)T_ * DR_];
__device__ __half g_ctx16[(long)T_ * H_ * DV_];
__device__ __half g_wqac[(long)HIDDEN_ * NMERGE_];
__device__ __half g_wqb [(long)QL_ * (H_ * DQK_)];
__device__ __half g_wkvb[(long)KVL_ * (H_ * (DN_ + DV_))];
__device__ __half g_wo  [(long)(H_ * DV_) * HIDDEN_];

// ------------------------------ helpers ------------------------------------
__device__ __forceinline__ void mma_f16(float* d, const unsigned* a, const unsigned* b) {
    asm volatile(
        "mma.sync.aligned.m16n8k16.row.col.f32.f16.f16.f32 "
        "{%0,%1,%2,%3}, {%4,%5,%6,%7}, {%8,%9}, {%0,%1,%2,%3};"
        : "+f"(d[0]), "+f"(d[1]), "+f"(d[2]), "+f"(d[3])
        : "r"(a[0]), "r"(a[1]), "r"(a[2]), "r"(a[3]),
          "r"(b[0]), "r"(b[1]));
}

__device__ __forceinline__ void ldsm_x4(unsigned* r, unsigned addr) {
    asm volatile("ldmatrix.sync.aligned.m8n8.x4.shared.b16 {%0,%1,%2,%3}, [%4];"
                 : "=r"(r[0]), "=r"(r[1]), "=r"(r[2]), "=r"(r[3]) : "r"(addr));
}
__device__ __forceinline__ void ldsm_x4t(unsigned* r, unsigned addr) {
    asm volatile("ldmatrix.sync.aligned.m8n8.x4.trans.shared.b16 {%0,%1,%2,%3}, [%4];"
                 : "=r"(r[0]), "=r"(r[1]), "=r"(r[2]), "=r"(r[3]) : "r"(addr));
}

__device__ __forceinline__ unsigned smem_u32(const void* p) {
    return (unsigned)__cvta_generic_to_shared(p);
}
__device__ __forceinline__ void cp16(unsigned dst, const void* src) {
    asm volatile("cp.async.cg.shared.global [%0], [%1], 16;\n" :: "r"(dst), "l"(src));
}
__device__ __forceinline__ unsigned exp2_f16x2(float lo, float hi) {
    unsigned h;
    asm("cvt.rn.f16x2.f32 %0, %1, %2;" : "=r"(h) : "f"(hi), "f"(lo));
    asm("ex2.approx.f16x2 %0, %0;" : "+r"(h));
    return h;
}

// ------------------------------- FP16 GEMM ---------------------------------
// C[M,N] = A @ B. Tile 128x128x64, warp grid 4(M)x2(N), warp tile 32x64.
// 3-stage cp.async, 2 CTAs/SM. OUT: 0 = float C, 1 = half C.
template<int OUT>
__global__ __launch_bounds__(256, 2)
void hgemm_kernel(const __half* __restrict__ A,
                  const __half* __restrict__ B,
                  void* __restrict__ Cv,
                  int M, int N, int K,
                  int lda, int ldb, int ldc)
{
    constexpr int BK = 64, S = 3;
    const int bx = blockIdx.x, by = blockIdx.y;

    extern __shared__ __half hsm[];

    const int tid  = threadIdx.x;
    const int lane = tid & 31;
    const int warp = tid >> 5;
    const int gid  = lane >> 2;
    const int tig  = lane & 3;
    const int wr   = warp & 3;
    const int wc   = warp >> 2;
    const int rowBase = by * 128, colBase = bx * 128;
    const int wm = wr * 32, wn = wc * 64;

    const int tiles = K / BK;

    auto load_tile = [&](int st, int kt) {
        const int k0 = kt * BK;
        __half* As = hsm + st * STG_H;
        __half* Bs = As + ASTG_H;
        #pragma unroll
        for (int i = 0; i < 4; i++) {
            int c = tid + i * 256;
            int r = c >> 3, kc = (c & 7) * 8;
            cp16(smem_u32(As + r * APAD_H + kc),
                 A + (long)(rowBase + r) * lda + k0 + kc);
        }
        #pragma unroll
        for (int i = 0; i < 4; i++) {
            int c = tid + i * 256;
            int r = c >> 4, nc = (c & 15) * 8;
            cp16(smem_u32(Bs + r * BPAD_H + nc),
                 B + (long)(k0 + r) * ldb + colBase + nc);
        }
    };

    #pragma unroll
    for (int s = 0; s < S - 1; s++) {
        load_tile(s, s);
        asm volatile("cp.async.commit_group;\n");
    }

    float acc[2][8][4];
    #pragma unroll
    for (int i = 0; i < 2; i++)
        #pragma unroll
        for (int j = 0; j < 8; j++)
            #pragma unroll
            for (int v = 0; v < 4; v++) acc[i][j][v] = 0.0f;

    const int arow = lane & 15;
    const int acol = (lane >> 4) * 8;

    for (int t = 0; t < tiles; t++) {
        asm volatile("cp.async.wait_group %0;\n" :: "n"(S - 2));
        __syncthreads();

        int tn = t + S - 1;
        if (tn < tiles) load_tile(tn % S, tn);
        asm volatile("cp.async.commit_group;\n");

        const __half* Asb = hsm + (t % S) * STG_H;
        const __half* Bsb = Asb + ASTG_H;

        #pragma unroll
        for (int ks = 0; ks < 4; ks++) {
            const int kb = ks * 16;
            unsigned af[2][4];
            unsigned a0 = smem_u32(Asb + (wm + arow) * APAD_H + kb + acol);
            ldsm_x4(af[0], a0);
            ldsm_x4(af[1], a0 + 16 * APAD_H * 2);

            unsigned b0 = smem_u32(Bsb + (kb + arow) * BPAD_H + wn + acol);
            #pragma unroll
            for (int p = 0; p < 4; p++) {
                unsigned bf[4];
                ldsm_x4t(bf, b0 + p * 32);
                mma_f16(acc[0][2 * p    ], af[0], bf + 0);
                mma_f16(acc[0][2 * p + 1], af[0], bf + 2);
                mma_f16(acc[1][2 * p    ], af[1], bf + 0);
                mma_f16(acc[1][2 * p + 1], af[1], bf + 2);
            }
        }
    }

    #pragma unroll
    for (int mt = 0; mt < 2; mt++) {
        #pragma unroll
        for (int nt = 0; nt < 8; nt++) {
            int gc = colBase + wn + nt * 8 + tig * 2;
            #pragma unroll
            for (int half = 0; half < 2; half++) {
                int gr = rowBase + wm + mt * 16 + gid + half * 8;
                float x0 = acc[mt][nt][half * 2];
                float x1 = acc[mt][nt][half * 2 + 1];
                if (OUT == 0) {
                    float* C = (float*)Cv;
                    *reinterpret_cast<float2*>(&C[(long)gr * ldc + gc]) =
                        make_float2(x0, x1);
                } else {
                    __half* C = (__half*)Cv;
                    *reinterpret_cast<__half2*>(&C[(long)gr * ldc + gc]) =
                        __floats2half2_rn(x0, x1);
                }
            }
        }
    }
}

// --------------------- fused flash attention (fp16 mma) --------------------
__global__ __launch_bounds__(128, 2)
void fused_attn_kernel(const __half* __restrict__ q,
                       const __half* __restrict__ kv,
                       const __half* __restrict__ kr,
                       __half* __restrict__ ctx)
{
    extern __shared__ __half hs[];
    __half* Qs = hs;
    __half* Ks = hs + AQ_B;
    __half* Vs = hs + AQ_B + AK_B;

    const int qt = 31 - blockIdx.x;
    const int h  = blockIdx.y;
    const int q0 = qt * 64;
    const int jmax = qt / 2 + 1;

    const int tid  = threadIdx.x;
    const int lane = tid & 31;
    const int warp = tid >> 5;
    const int gid  = lane >> 2;
    const int tig  = lane & 3;
    const int wm   = warp * 16;
    const int KVROW = H_ * (DN_ + DV_);

    const int arow = lane & 15;
    const int acol = (lane >> 4) * 8;
    const int krow_off = ((lane >> 4) << 3) + (lane & 7);
    const int kcol_off = ((lane >> 3) & 1) << 3;

    auto load_K = [&](int j) {
        const long key0 = (long)j * 128;
        #pragma unroll
        for (int i = 0; i < 24; i++) {
            int e = tid + i * 128;
            int r = e / 24;
            int fc = (e % 24) * 8;
            const __half* src = (fc < DN_)
                ? kv + (key0 + r) * (long)KVROW + h * (DN_ + DV_) + fc
                : kr + (key0 + r) * (long)DR_ + (fc - DN_);
            cp16(smem_u32(Ks + r * KPAD_B + fc), src);
        }
    };
    auto load_V = [&](int j) {
        const long key0 = (long)j * 128;
        #pragma unroll
        for (int i = 0; i < 16; i++) {
            int e = tid + i * 128;
            int r = e >> 4;
            int fc = (e & 15) * 8;
            cp16(smem_u32(Vs + r * VPAD_B + fc),
                 kv + (key0 + r) * (long)KVROW + h * (DN_ + DV_) + DN_ + fc);
        }
    };

    const __half* Qbase = q + (long)q0 * (H_ * DQK_) + h * DQK_;
    #pragma unroll
    for (int i = 0; i < 12; i++) {
        int e = tid + i * 128;
        int r = e / 24;
        int fc = (e % 24) * 8;
        cp16(smem_u32(Qs + r * QPAD_B + fc), Qbase + (long)r * (H_ * DQK_) + fc);
    }
    load_K(0);
    asm volatile("cp.async.commit_group;\n");

    float m0 = -1e30f, m1 = -1e30f, l0 = 0.0f, l1 = 0.0f;
    float Oacc[16][4];
    #pragma unroll
    for (int i = 0; i < 16; i++)
        #pragma unroll
        for (int v = 0; v < 4; v++) Oacc[i][v] = 0.0f;

    const int row_g0 = q0 + wm + gid;
    const int row_g1 = row_g0 + 8;

    for (int j = 0; j < jmax; j++) {
        const bool diag = (j == jmax - 1);
        const int key0 = j * 128;

        load_V(j);
        asm volatile("cp.async.commit_group;\n");
        asm volatile("cp.async.wait_group 1;\n");
        __syncthreads();

        float Sacc[16][4];
        #pragma unroll
        for (int i = 0; i < 16; i++)
            #pragma unroll
            for (int v = 0; v < 4; v++) Sacc[i][v] = 0.0f;

        #pragma unroll
        for (int ks = 0; ks < 12; ks++) {
            const int kb = ks * 16;
            unsigned af[4];
            ldsm_x4(af, smem_u32(Qs + (wm + arow) * QPAD_B + kb + acol));
            #pragma unroll
            for (int nt2 = 0; nt2 < 8; nt2++) {
                unsigned bf[4];
                ldsm_x4(bf, smem_u32(Ks + (nt2 * 16 + krow_off) * KPAD_B
                                     + kb + kcol_off));
                mma_f16(Sacc[2 * nt2    ], af, bf + 0);
                mma_f16(Sacc[2 * nt2 + 1], af, bf + 2);
            }
        }
        __syncthreads();

        if (j + 1 < jmax) {
            load_K(j + 1);
            asm volatile("cp.async.commit_group;\n");
        }

        #pragma unroll
        for (int nt = 0; nt < 16; nt++)
            #pragma unroll
            for (int v = 0; v < 4; v++) {
                int key_g = key0 + nt * 8 + tig * 2 + (v & 1);
                int row_g = (v >> 1) ? row_g1 : row_g0;
                float s = Sacc[nt][v] * SC2_;
                if (diag && key_g > row_g) s = -1e30f;
                Sacc[nt][v] = s;
            }

        float mx0 = -1e30f, mx1 = -1e30f;
        #pragma unroll
        for (int nt = 0; nt < 16; nt++) {
            mx0 = fmaxf(mx0, fmaxf(Sacc[nt][0], Sacc[nt][1]));
            mx1 = fmaxf(mx1, fmaxf(Sacc[nt][2], Sacc[nt][3]));
        }
        mx0 = fmaxf(mx0, __shfl_xor_sync(0xffffffffu, mx0, 1));
        mx0 = fmaxf(mx0, __shfl_xor_sync(0xffffffffu, mx0, 2));
        mx1 = fmaxf(mx1, __shfl_xor_sync(0xffffffffu, mx1, 1));
        mx1 = fmaxf(mx1, __shfl_xor_sync(0xffffffffu, mx1, 2));

        float mn0 = fmaxf(m0, mx0), mn1 = fmaxf(m1, mx1);
        float r0 = exp2f(m0 - mn0), r1 = exp2f(m1 - mn1);
        m0 = mn0; m1 = mn1;

        #pragma unroll
        for (int nt = 0; nt < 16; nt++) {
            Oacc[nt][0] *= r0; Oacc[nt][1] *= r0;
            Oacc[nt][2] *= r1; Oacc[nt][3] *= r1;
        }

        unsigned pa[8][4];
        float s0 = 0.0f, s1 = 0.0f;
        #pragma unroll
        for (int c = 0; c < 8; c++) {
            pa[c][0] = exp2_f16x2(Sacc[2 * c][0] - m0, Sacc[2 * c][1] - m0);
            pa[c][1] = exp2_f16x2(Sacc[2 * c][2] - m1, Sacc[2 * c][3] - m1);
            pa[c][2] = exp2_f16x2(Sacc[2 * c + 1][0] - m0, Sacc[2 * c + 1][1] - m0);
            pa[c][3] = exp2_f16x2(Sacc[2 * c + 1][2] - m1, Sacc[2 * c + 1][3] - m1);
            float2 p;
            p = __half22float2(*reinterpret_cast<__half2*>(&pa[c][0])); s0 += p.x + p.y;
            p = __half22float2(*reinterpret_cast<__half2*>(&pa[c][2])); s0 += p.x + p.y;
            p = __half22float2(*reinterpret_cast<__half2*>(&pa[c][1])); s1 += p.x + p.y;
            p = __half22float2(*reinterpret_cast<__half2*>(&pa[c][3])); s1 += p.x + p.y;
        }
        s0 += __shfl_xor_sync(0xffffffffu, s0, 1);
        s0 += __shfl_xor_sync(0xffffffffu, s0, 2);
        s1 += __shfl_xor_sync(0xffffffffu, s1, 1);
        s1 += __shfl_xor_sync(0xffffffffu, s1, 2);
        l0 = l0 * r0 + s0;
        l1 = l1 * r1 + s1;

        asm volatile("cp.async.wait_group %0;\n" :: "n"(1) : "memory");
        if (j + 1 >= jmax)
            asm volatile("cp.async.wait_group 0;\n" ::: "memory");
        __syncthreads();

        #pragma unroll
        for (int c = 0; c < 8; c++) {
            const int kc = c * 16;
            unsigned vb = smem_u32(Vs + (kc + arow) * VPAD_B + acol);
            #pragma unroll
            for (int p = 0; p < 8; p++) {
                unsigned bf[4];
                ldsm_x4t(bf, vb + p * 32);
                mma_f16(Oacc[2 * p    ], pa[c], bf + 0);
                mma_f16(Oacc[2 * p + 1], pa[c], bf + 2);
            }
        }
        __syncthreads();
    }

    const float inv0 = 1.0f / l0, inv1 = 1.0f / l1;
    #pragma unroll
    for (int nt = 0; nt < 16; nt++) {
        int cl = nt * 8 + tig * 2;
        *reinterpret_cast<__half2*>(
            &ctx[(long)row_g0 * (H_ * DV_) + h * DV_ + cl]) =
            __floats2half2_rn(Oacc[nt][0] * inv0, Oacc[nt][1] * inv0);
        *reinterpret_cast<__half2*>(
            &ctx[(long)row_g1 * (H_ * DV_) + h * DV_ + cl]) =
            __floats2half2_rn(Oacc[nt][2] * inv1, Oacc[nt][3] * inv1);
    }
}

// ------------------------------ prep kernels --------------------------------
__global__ void convert4_kernel(const float* s0, __half* d0, long c0,
                                const float* s1, __half* d1, long c1,
                                const float* s2, __half* d2, long c2,
                                const float* s3, __half* d3, long c3)
{
    long i = (long)blockIdx.x * blockDim.x + threadIdx.x;
    const float* s; __half* d;
    if (i < c0)                { s = s0; d = d0; }
    else if ((i -= c0) < c1)   { s = s1; d = d1; }
    else if ((i -= c1) < c2)   { s = s2; d = d2; }
    else if ((i -= c2) < c3)   { s = s3; d = d3; }
    else return;
    long e = i * 4;
    float4 v = *reinterpret_cast<const float4*>(s + e);
    union { __half2 h[2]; uint2 u; } cv;
    cv.h[0] = __floats2half2_rn(v.x, v.y);
    cv.h[1] = __floats2half2_rn(v.z, v.w);
    *reinterpret_cast<uint2*>(d + e) = cv.u;
}

__global__ void tohalf8_strided(const float* __restrict__ in, int ldin, int Cin,
                                __half* __restrict__ out, int ldout, int chunks)
{
    long idx = (long)blockIdx.x * blockDim.x + threadIdx.x;
    int r  = (int)(idx / chunks);
    int c  = (int)(idx % chunks) * 8;
    union { __half2 h[4]; uint4 u; } cv;
    if (c < Cin) {
        const float* src = in + (long)r * ldin + c;
        float4 a = *reinterpret_cast<const float4*>(src);
        float4 b = *reinterpret_cast<const float4*>(src + 4);
        cv.h[0] = __floats2half2_rn(a.x, a.y);
        cv.h[1] = __floats2half2_rn(a.z, a.w);
        cv.h[2] = __floats2half2_rn(b.x, b.y);
        cv.h[3] = __floats2half2_rn(b.z, b.w);
    } else {
        cv.u = make_uint4(0, 0, 0, 0);
    }
    *reinterpret_cast<uint4*>(out + (long)r * ldout + c) = cv.u;
}

// ------------------------------ RMSNorm (half out) --------------------------
__global__ void rmsnorm_h_kernel(const float* __restrict__ x,
                                 const float* __restrict__ w,
                                 __half* __restrict__ y,
                                 int L, int ldx, int ldy)
{
    const int row = blockIdx.x, tid = threadIdx.x;
    const float* xr = x + (long)row * ldx;
    __half* yr = y + (long)row * ldy;

    __shared__ float red[256];
    float s = 0.0f;
    for (int i = tid; i < L; i += 256) { float v = xr[i]; s += v * v; }
    red[tid] = s; __syncthreads();
    for (int o = 128; o > 0; o >>= 1) {
        if (tid < o) red[tid] += red[tid + o];
        __syncthreads();
    }
    const float scale = rsqrtf(red[0] / (float)L + EPS_);
    for (int i = tid; i < L; i += 256)
        yr[i] = __float2half_rn(xr[i] * scale * w[i]);
}

// -------------------------------- RoPE --------------------------------------
__global__ void rope_q_kernel(__half* __restrict__ q,
                              const float* __restrict__ cosT,
                              const float* __restrict__ sinT)
{
    const int t = blockIdx.x;
    const int w = threadIdx.x >> 5, lane = threadIdx.x & 31;
    const float c = cosT[(long)t * DR_ + lane];
    const float s = sinT[(long)t * DR_ + lane];
    #pragma unroll
    for (int it = 0; it < 4; it++) {
        int h = it * 8 + w;
        __half* p = q + (long)t * (H_ * DQK_) + h * DQK_ + DN_;
        __half2 v = *reinterpret_cast<const __half2*>(p + 2 * lane);
        float lo = __half2float(v.x), hi = __half2float(v.y);
        __syncwarp();
        p[lane]      = __float2half_rn(lo * c - hi * s);
        p[lane + 32] = __float2half_rn(hi * c + lo * s);
    }
}

__global__ void rope_k_kernel(const float* __restrict__ ckv_pe,
                              __half* __restrict__ kr,
                              const float* __restrict__ cosT,
                              const float* __restrict__ sinT, int ld)
{
    const int t = blockIdx.x * 8 + (threadIdx.x >> 5);
    const int lane = threadIdx.x & 31;
    const float c = cosT[(long)t * DR_ + lane];
    const float s = sinT[(long)t * DR_ + lane];
    float2 v = *reinterpret_cast<const float2*>(ckv_pe + (long)t * ld + 2 * lane);
    __half* o = kr + (long)t * DR_;
    o[lane]      = __float2half_rn(v.x * c - v.y * s);
    o[lane + 32] = __float2half_rn(v.y * c + v.x * s);
}

// ------------------------------- launch ------------------------------------
extern "C" void kernel_launch(void* const* d_in, const int* in_sizes, int n_in,
                              void* d_out, int out_size)
{
    const float* hidden = (const float*)d_in[0];
    const float* cosT   = (const float*)d_in[1];
    const float* sinT   = (const float*)d_in[2];
    const float* wq_a   = (const float*)d_in[3];
    const float* q_ln   = (const float*)d_in[4];
    const float* wq_b   = (const float*)d_in[5];
    const float* wkv_a  = (const float*)d_in[6];
    const float* kv_ln  = (const float*)d_in[7];
    const float* wkv_b  = (const float*)d_in[8];
    const float* wo     = (const float*)d_in[9];
    float* out = (float*)d_out;

    static __half *hidH = nullptr, *qa16 = nullptr, *q16 = nullptr,
                  *cn16 = nullptr, *kv16 = nullptr, *kr16 = nullptr,
                  *ctx16 = nullptr, *wqac = nullptr, *wqb = nullptr,
                  *wkvb = nullptr, *woH = nullptr;
    static float *qack = nullptr;
    static cudaStream_t s2 = nullptr;
    static cudaEvent_t evFork, evQA, evW, evA, evB;
    if (!qack) {
        cudaGetSymbolAddress((void**)&hidH,  g_hidH);
        cudaGetSymbolAddress((void**)&qack,  g_qack);
        cudaGetSymbolAddress((void**)&qa16,  g_qa16);
        cudaGetSymbolAddress((void**)&q16,   g_q16);
        cudaGetSymbolAddress((void**)&cn16,  g_cn16);
        cudaGetSymbolAddress((void**)&kv16,  g_kv16);
        cudaGetSymbolAddress((void**)&kr16,  g_kr16);
        cudaGetSymbolAddress((void**)&ctx16, g_ctx16);
        cudaGetSymbolAddress((void**)&wqac,  g_wqac);
        cudaGetSymbolAddress((void**)&wqb,   g_wqb);
        cudaGetSymbolAddress((void**)&wkvb,  g_wkvb);
        cudaGetSymbolAddress((void**)&woH,   g_wo);
        cudaFuncSetAttribute(hgemm_kernel<0>,
                             cudaFuncAttributeMaxDynamicSharedMemorySize, GSMEM_BYTES);
        cudaFuncSetAttribute(hgemm_kernel<1>,
                             cudaFuncAttributeMaxDynamicSharedMemorySize, GSMEM_BYTES);
        cudaFuncSetAttribute(fused_attn_kernel,
                             cudaFuncAttributeMaxDynamicSharedMemorySize, FUSED_SMEM);
        cudaStreamCreateWithFlags(&s2, cudaStreamNonBlocking);
        cudaEventCreateWithFlags(&evFork, cudaEventDisableTiming);
        cudaEventCreateWithFlags(&evQA,   cudaEventDisableTiming);
        cudaEventCreateWithFlags(&evW,    cudaEventDisableTiming);
        cudaEventCreateWithFlags(&evA,    cudaEventDisableTiming);
        cudaEventCreateWithFlags(&evB,    cudaEventDisableTiming);
    }

    const dim3 blk(256);

    // ---- fork second stream
    cudaEventRecord(evFork, 0);
    cudaStreamWaitEvent(s2, evFork, 0);

    // s2: merged A-proj weights first (critical path of merged GEMM) ...
    tohalf8_strided<<<(HIDDEN_ * (QL_ / 8)) / 256, 256, 0, s2>>>(
        wq_a, QL_, QL_, wqac, NMERGE_, QL_ / 8);
    tohalf8_strided<<<(HIDDEN_ * (CKVP_ / 8)) / 256, 256, 0, s2>>>(
        wkv_a, KVL_ + DR_, KVL_ + DR_, wqac + QL_, NMERGE_, CKVP_ / 8);
    cudaEventRecord(evQA, s2);
    // ... then the B/O weights (needed later by GEMM3/6/out)
    const long c1 = (long)QL_ * (H_ * DQK_) / 4;
    const long c2 = (long)KVL_ * (H_ * (DN_ + DV_)) / 4;
    const long c3 = (long)(H_ * DV_) * HIDDEN_ / 4;
    convert4_kernel<<<(int)((c1 + c2 + c3 + 255) / 256), 256, 0, s2>>>(
        wq_b, wqb, c1, wkv_b, wkvb, c2, wo, woH, c3, nullptr, nullptr, 0);
    cudaEventRecord(evW, s2);

    // s0: hidden convert (runs concurrently with wqac converts on s2)
    const long c0 = (long)T_ * HIDDEN_ / 4;
    convert4_kernel<<<(int)((c0 + 255) / 256), 256>>>(
        hidden, hidH, c0, nullptr, nullptr, 0, nullptr, nullptr, 0,
        nullptr, nullptr, 0);

    // merged GEMM: needs hidH (s0) + wqac (s2)
    cudaStreamWaitEvent(0, evQA, 0);
    hgemm_kernel<0><<<dim3(NMERGE_ / 128, 16), blk, GSMEM_BYTES>>>(
        hidH, wqac, qack, T_, NMERGE_, HIDDEN_, HIDDEN_, NMERGE_, NMERGE_);
    cudaEventRecord(evA, 0);

    // kv chain on s2
    cudaStreamWaitEvent(s2, evA, 0);
    rmsnorm_h_kernel<<<T_, 256, 0, s2>>>(qack + QL_, kv_ln, cn16, KVL_, NMERGE_, KVL_);
    hgemm_kernel<1><<<dim3(H_ * (DN_ + DV_) / 128, 16), blk, GSMEM_BYTES, s2>>>(
        cn16, wkvb, kv16, T_, H_ * (DN_ + DV_), KVL_,
        KVL_, H_ * (DN_ + DV_), H_ * (DN_ + DV_));
    rope_k_kernel<<<T_ / 8, 256, 0, s2>>>(qack + QL_ + KVL_, kr16, cosT, sinT, NMERGE_);
    cudaEventRecord(evB, s2);

    // q chain on main stream
    rmsnorm_h_kernel<<<T_, 256>>>(qack, q_ln, qa16, QL_, NMERGE_, QL_);
    cudaStreamWaitEvent(0, evW, 0);
    hgemm_kernel<1><<<dim3(H_ * DQK_ / 128, 16), blk, GSMEM_BYTES>>>(
        qa16, wqb, q16, T_, H_ * DQK_, QL_, QL_, H_ * DQK_, H_ * DQK_);
    rope_q_kernel<<<T_, 256>>>(q16, cosT, sinT);

    // join + attention + out GEMM
    cudaStreamWaitEvent(0, evB, 0);
    fused_attn_kernel<<<dim3(32, H_), 128, FUSED_SMEM>>>(q16, kv16, kr16, ctx16);
    hgemm_kernel<0><<<dim3(HIDDEN_ / 128, 16), blk, GSMEM_BYTES>>>(
        ctx16, woH, out, T_, HIDDEN_, H_ * DV_, H_ * DV_, HIDDEN_, HIDDEN_);
}

// round 17
// speedup vs baseline: 1.0716x; 1.0098x over previous
#include <cuda_runtime.h>
#include <cuda_fp16.h>
#include <math.h>

// ---------------------------------------------------------------------------
// DeepSeek V2 MLA attention prefill — fp16 mma.sync m16n8k16 + ldmatrix.
// Dense GEMMs: 128x128x64 tiles, 8 warps, 3-stage cp.async, 2 CTAs/SM.
// Attention: 64-row q-tiles, register softmax + register P.
// Row-half pipeline: GEMM3/rope/attention/out-GEMM split top/bottom across
// two streams so heavy attention starts after half of GEMM3.
// ---------------------------------------------------------------------------

namespace {
constexpr int T_      = 2048;
constexpr int H_      = 32;
constexpr int HIDDEN_ = 5120;
constexpr int QL_     = 1536;
constexpr int KVL_    = 512;
constexpr int DN_     = 128;
constexpr int DR_     = 64;
constexpr int DQK_    = 192;
constexpr int DV_     = 128;
constexpr int CKVP_   = 640;
constexpr int NMERGE_ = QL_ + CKVP_;         // 2176
constexpr float EPS_  = 1e-6f;
constexpr float SC2_  = 0.07216878364870323f * 1.4426950408889634f;

// fp16 dense GEMM smem (halves), tile 128x128x64, 3 stages
constexpr int APAD_H = 72;
constexpr int BPAD_H = 136;
constexpr int ASTG_H = 128 * APAD_H;
constexpr int BSTG_H = 64 * BPAD_H;
constexpr int STG_H  = ASTG_H + BSTG_H;
constexpr int GSMEM_BYTES = 3 * STG_H * 2;   // 107520 B

// fused attention smem (halves): Q 64x200, K 128x200, V 128x136
constexpr int QPAD_B = 200;
constexpr int KPAD_B = 200;
constexpr int VPAD_B = 136;
constexpr int AQ_B   = 64 * QPAD_B;
constexpr int AK_B   = 128 * KPAD_B;
constexpr int AV_B   = 128 * VPAD_B;
constexpr int FUSED_SMEM = (AQ_B + AK_B + AV_B) * 2;   // 111616 B
}

// ------------------------- scratch (static device) -------------------------
__device__ __half g_hidH[(long)T_ * HIDDEN_];
__device__ float  g_qack[(long)T_ * NMERGE_];
__device__ __half g_qa16[(long)T_ * QL_];
__device__ __half g_q16[(long)T_ * H_ * DQK_];
__device__ __half g_cn16[(long)T_ * KVL_];
__device__ __half g_kv16[(long)T_ * H_ * (DN_ + DV_)];
__device__ __half g_kr16[(long)T_ * DR_];
__device__ __half g_ctx16[(long)T_ * H_ * DV_];
__device__ __half g_wqac[(long)HIDDEN_ * NMERGE_];
__device__ __half g_wqb [(long)QL_ * (H_ * DQK_)];
__device__ __half g_wkvb[(long)KVL_ * (H_ * (DN_ + DV_))];
__device__ __half g_wo  [(long)(H_ * DV_) * HIDDEN_];

// ------------------------------ helpers ------------------------------------
__device__ __forceinline__ void mma_f16(float* d, const unsigned* a, const unsigned* b) {
    asm volatile(
        "mma.sync.aligned.m16n8k16.row.col.f32.f16.f16.f32 "
        "{%0,%1,%2,%3}, {%4,%5,%6,%7}, {%8,%9}, {%0,%1,%2,%3};"
        : "+f"(d[0]), "+f"(d[1]), "+f"(d[2]), "+f"(d[3])
        : "r"(a[0]), "r"(a[1]), "r"(a[2]), "r"(a[3]),
          "r"(b[0]), "r"(b[1]));
}

__device__ __forceinline__ void ldsm_x4(unsigned* r, unsigned addr) {
    asm volatile("ldmatrix.sync.aligned.m8n8.x4.shared.b16 {%0,%1,%2,%3}, [%4];"
                 : "=r"(r[0]), "=r"(r[1]), "=r"(r[2]), "=r"(r[3]) : "r"(addr));
}
__device__ __forceinline__ void ldsm_x4t(unsigned* r, unsigned addr) {
    asm volatile("ldmatrix.sync.aligned.m8n8.x4.trans.shared.b16 {%0,%1,%2,%3}, [%4];"
                 : "=r"(r[0]), "=r"(r[1]), "=r"(r[2]), "=r"(r[3]) : "r"(addr));
}

__device__ __forceinline__ unsigned smem_u32(const void* p) {
    return (unsigned)__cvta_generic_to_shared(p);
}
__device__ __forceinline__ void cp16(unsigned dst, const void* src) {
    asm volatile("cp.async.cg.shared.global [%0], [%1], 16;\n" :: "r"(dst), "l"(src));
}
__device__ __forceinline__ unsigned exp2_f16x2(float lo, float hi) {
    unsigned h;
    asm("cvt.rn.f16x2.f32 %0, %1, %2;" : "=r"(h) : "f"(hi), "f"(lo));
    asm("ex2.approx.f16x2 %0, %0;" : "+r"(h));
    return h;
}

// ------------------------------- FP16 GEMM ---------------------------------
// C[M,N] = A @ B. Tile 128x128x64, warp grid 4(M)x2(N), warp tile 32x64.
template<int OUT>
__global__ __launch_bounds__(256, 2)
void hgemm_kernel(const __half* __restrict__ A,
                  const __half* __restrict__ B,
                  void* __restrict__ Cv,
                  int M, int N, int K,
                  int lda, int ldb, int ldc)
{
    constexpr int BK = 64, S = 3;
    const int bx = blockIdx.x, by = blockIdx.y;

    extern __shared__ __half hsm[];

    const int tid  = threadIdx.x;
    const int lane = tid & 31;
    const int warp = tid >> 5;
    const int gid  = lane >> 2;
    const int tig  = lane & 3;
    const int wr   = warp & 3;
    const int wc   = warp >> 2;
    const int rowBase = by * 128, colBase = bx * 128;
    const int wm = wr * 32, wn = wc * 64;

    const int tiles = K / BK;

    auto load_tile = [&](int st, int kt) {
        const int k0 = kt * BK;
        __half* As = hsm + st * STG_H;
        __half* Bs = As + ASTG_H;
        #pragma unroll
        for (int i = 0; i < 4; i++) {
            int c = tid + i * 256;
            int r = c >> 3, kc = (c & 7) * 8;
            cp16(smem_u32(As + r * APAD_H + kc),
                 A + (long)(rowBase + r) * lda + k0 + kc);
        }
        #pragma unroll
        for (int i = 0; i < 4; i++) {
            int c = tid + i * 256;
            int r = c >> 4, nc = (c & 15) * 8;
            cp16(smem_u32(Bs + r * BPAD_H + nc),
                 B + (long)(k0 + r) * ldb + colBase + nc);
        }
    };

    #pragma unroll
    for (int s = 0; s < S - 1; s++) {
        load_tile(s, s);
        asm volatile("cp.async.commit_group;\n");
    }

    float acc[2][8][4];
    #pragma unroll
    for (int i = 0; i < 2; i++)
        #pragma unroll
        for (int j = 0; j < 8; j++)
            #pragma unroll
            for (int v = 0; v < 4; v++) acc[i][j][v] = 0.0f;

    const int arow = lane & 15;
    const int acol = (lane >> 4) * 8;

    for (int t = 0; t < tiles; t++) {
        asm volatile("cp.async.wait_group %0;\n" :: "n"(S - 2));
        __syncthreads();

        int tn = t + S - 1;
        if (tn < tiles) load_tile(tn % S, tn);
        asm volatile("cp.async.commit_group;\n");

        const __half* Asb = hsm + (t % S) * STG_H;
        const __half* Bsb = Asb + ASTG_H;

        #pragma unroll
        for (int ks = 0; ks < 4; ks++) {
            const int kb = ks * 16;
            unsigned af[2][4];
            unsigned a0 = smem_u32(Asb + (wm + arow) * APAD_H + kb + acol);
            ldsm_x4(af[0], a0);
            ldsm_x4(af[1], a0 + 16 * APAD_H * 2);

            unsigned b0 = smem_u32(Bsb + (kb + arow) * BPAD_H + wn + acol);
            #pragma unroll
            for (int p = 0; p < 4; p++) {
                unsigned bf[4];
                ldsm_x4t(bf, b0 + p * 32);
                mma_f16(acc[0][2 * p    ], af[0], bf + 0);
                mma_f16(acc[0][2 * p + 1], af[0], bf + 2);
                mma_f16(acc[1][2 * p    ], af[1], bf + 0);
                mma_f16(acc[1][2 * p + 1], af[1], bf + 2);
            }
        }
    }

    #pragma unroll
    for (int mt = 0; mt < 2; mt++) {
        #pragma unroll
        for (int nt = 0; nt < 8; nt++) {
            int gc = colBase + wn + nt * 8 + tig * 2;
            #pragma unroll
            for (int half = 0; half < 2; half++) {
                int gr = rowBase + wm + mt * 16 + gid + half * 8;
                float x0 = acc[mt][nt][half * 2];
                float x1 = acc[mt][nt][half * 2 + 1];
                if (OUT == 0) {
                    float* C = (float*)Cv;
                    *reinterpret_cast<float2*>(&C[(long)gr * ldc + gc]) =
                        make_float2(x0, x1);
                } else {
                    __half* C = (__half*)Cv;
                    *reinterpret_cast<__half2*>(&C[(long)gr * ldc + gc]) =
                        __floats2half2_rn(x0, x1);
                }
            }
        }
    }
}

// --------------------- fused flash attention (fp16 mma) --------------------
// qt = qt_base - blockIdx.x  (heavy-first within each launch half)
__global__ __launch_bounds__(128, 2)
void fused_attn_kernel(const __half* __restrict__ q,
                       const __half* __restrict__ kv,
                       const __half* __restrict__ kr,
                       __half* __restrict__ ctx, int qt_base)
{
    extern __shared__ __half hs[];
    __half* Qs = hs;
    __half* Ks = hs + AQ_B;
    __half* Vs = hs + AQ_B + AK_B;

    const int qt = qt_base - blockIdx.x;
    const int h  = blockIdx.y;
    const int q0 = qt * 64;
    const int jmax = qt / 2 + 1;

    const int tid  = threadIdx.x;
    const int lane = tid & 31;
    const int warp = tid >> 5;
    const int gid  = lane >> 2;
    const int tig  = lane & 3;
    const int wm   = warp * 16;
    const int KVROW = H_ * (DN_ + DV_);

    const int arow = lane & 15;
    const int acol = (lane >> 4) * 8;
    const int krow_off = ((lane >> 4) << 3) + (lane & 7);
    const int kcol_off = ((lane >> 3) & 1) << 3;

    auto load_K = [&](int j) {
        const long key0 = (long)j * 128;
        #pragma unroll
        for (int i = 0; i < 24; i++) {
            int e = tid + i * 128;
            int r = e / 24;
            int fc = (e % 24) * 8;
            const __half* src = (fc < DN_)
                ? kv + (key0 + r) * (long)KVROW + h * (DN_ + DV_) + fc
                : kr + (key0 + r) * (long)DR_ + (fc - DN_);
            cp16(smem_u32(Ks + r * KPAD_B + fc), src);
        }
    };
    auto load_V = [&](int j) {
        const long key0 = (long)j * 128;
        #pragma unroll
        for (int i = 0; i < 16; i++) {
            int e = tid + i * 128;
            int r = e >> 4;
            int fc = (e & 15) * 8;
            cp16(smem_u32(Vs + r * VPAD_B + fc),
                 kv + (key0 + r) * (long)KVROW + h * (DN_ + DV_) + DN_ + fc);
        }
    };

    const __half* Qbase = q + (long)q0 * (H_ * DQK_) + h * DQK_;
    #pragma unroll
    for (int i = 0; i < 12; i++) {
        int e = tid + i * 128;
        int r = e / 24;
        int fc = (e % 24) * 8;
        cp16(smem_u32(Qs + r * QPAD_B + fc), Qbase + (long)r * (H_ * DQK_) + fc);
    }
    load_K(0);
    asm volatile("cp.async.commit_group;\n");

    float m0 = -1e30f, m1 = -1e30f, l0 = 0.0f, l1 = 0.0f;
    float Oacc[16][4];
    #pragma unroll
    for (int i = 0; i < 16; i++)
        #pragma unroll
        for (int v = 0; v < 4; v++) Oacc[i][v] = 0.0f;

    const int row_g0 = q0 + wm + gid;
    const int row_g1 = row_g0 + 8;

    for (int j = 0; j < jmax; j++) {
        const bool diag = (j == jmax - 1);
        const int key0 = j * 128;

        load_V(j);
        asm volatile("cp.async.commit_group;\n");
        asm volatile("cp.async.wait_group 1;\n");
        __syncthreads();

        float Sacc[16][4];
        #pragma unroll
        for (int i = 0; i < 16; i++)
            #pragma unroll
            for (int v = 0; v < 4; v++) Sacc[i][v] = 0.0f;

        #pragma unroll
        for (int ks = 0; ks < 12; ks++) {
            const int kb = ks * 16;
            unsigned af[4];
            ldsm_x4(af, smem_u32(Qs + (wm + arow) * QPAD_B + kb + acol));
            #pragma unroll
            for (int nt2 = 0; nt2 < 8; nt2++) {
                unsigned bf[4];
                ldsm_x4(bf, smem_u32(Ks + (nt2 * 16 + krow_off) * KPAD_B
                                     + kb + kcol_off));
                mma_f16(Sacc[2 * nt2    ], af, bf + 0);
                mma_f16(Sacc[2 * nt2 + 1], af, bf + 2);
            }
        }
        __syncthreads();

        if (j + 1 < jmax) {
            load_K(j + 1);
            asm volatile("cp.async.commit_group;\n");
        }

        #pragma unroll
        for (int nt = 0; nt < 16; nt++)
            #pragma unroll
            for (int v = 0; v < 4; v++) {
                int key_g = key0 + nt * 8 + tig * 2 + (v & 1);
                int row_g = (v >> 1) ? row_g1 : row_g0;
                float s = Sacc[nt][v] * SC2_;
                if (diag && key_g > row_g) s = -1e30f;
                Sacc[nt][v] = s;
            }

        float mx0 = -1e30f, mx1 = -1e30f;
        #pragma unroll
        for (int nt = 0; nt < 16; nt++) {
            mx0 = fmaxf(mx0, fmaxf(Sacc[nt][0], Sacc[nt][1]));
            mx1 = fmaxf(mx1, fmaxf(Sacc[nt][2], Sacc[nt][3]));
        }
        mx0 = fmaxf(mx0, __shfl_xor_sync(0xffffffffu, mx0, 1));
        mx0 = fmaxf(mx0, __shfl_xor_sync(0xffffffffu, mx0, 2));
        mx1 = fmaxf(mx1, __shfl_xor_sync(0xffffffffu, mx1, 1));
        mx1 = fmaxf(mx1, __shfl_xor_sync(0xffffffffu, mx1, 2));

        float mn0 = fmaxf(m0, mx0), mn1 = fmaxf(m1, mx1);
        float r0 = exp2f(m0 - mn0), r1 = exp2f(m1 - mn1);
        m0 = mn0; m1 = mn1;

        #pragma unroll
        for (int nt = 0; nt < 16; nt++) {
            Oacc[nt][0] *= r0; Oacc[nt][1] *= r0;
            Oacc[nt][2] *= r1; Oacc[nt][3] *= r1;
        }

        unsigned pa[8][4];
        float s0 = 0.0f, s1 = 0.0f;
        #pragma unroll
        for (int c = 0; c < 8; c++) {
            pa[c][0] = exp2_f16x2(Sacc[2 * c][0] - m0, Sacc[2 * c][1] - m0);
            pa[c][1] = exp2_f16x2(Sacc[2 * c][2] - m1, Sacc[2 * c][3] - m1);
            pa[c][2] = exp2_f16x2(Sacc[2 * c + 1][0] - m0, Sacc[2 * c + 1][1] - m0);
            pa[c][3] = exp2_f16x2(Sacc[2 * c + 1][2] - m1, Sacc[2 * c + 1][3] - m1);
            float2 p;
            p = __half22float2(*reinterpret_cast<__half2*>(&pa[c][0])); s0 += p.x + p.y;
            p = __half22float2(*reinterpret_cast<__half2*>(&pa[c][2])); s0 += p.x + p.y;
            p = __half22float2(*reinterpret_cast<__half2*>(&pa[c][1])); s1 += p.x + p.y;
            p = __half22float2(*reinterpret_cast<__half2*>(&pa[c][3])); s1 += p.x + p.y;
        }
        s0 += __shfl_xor_sync(0xffffffffu, s0, 1);
        s0 += __shfl_xor_sync(0xffffffffu, s0, 2);
        s1 += __shfl_xor_sync(0xffffffffu, s1, 1);
        s1 += __shfl_xor_sync(0xffffffffu, s1, 2);
        l0 = l0 * r0 + s0;
        l1 = l1 * r1 + s1;

        asm volatile("cp.async.wait_group %0;\n" :: "n"(1) : "memory");
        if (j + 1 >= jmax)
            asm volatile("cp.async.wait_group 0;\n" ::: "memory");
        __syncthreads();

        #pragma unroll
        for (int c = 0; c < 8; c++) {
            const int kc = c * 16;
            unsigned vb = smem_u32(Vs + (kc + arow) * VPAD_B + acol);
            #pragma unroll
            for (int p = 0; p < 8; p++) {
                unsigned bf[4];
                ldsm_x4t(bf, vb + p * 32);
                mma_f16(Oacc[2 * p    ], pa[c], bf + 0);
                mma_f16(Oacc[2 * p + 1], pa[c], bf + 2);
            }
        }
        __syncthreads();
    }

    const float inv0 = 1.0f / l0, inv1 = 1.0f / l1;
    #pragma unroll
    for (int nt = 0; nt < 16; nt++) {
        int cl = nt * 8 + tig * 2;
        *reinterpret_cast<__half2*>(
            &ctx[(long)row_g0 * (H_ * DV_) + h * DV_ + cl]) =
            __floats2half2_rn(Oacc[nt][0] * inv0, Oacc[nt][1] * inv0);
        *reinterpret_cast<__half2*>(
            &ctx[(long)row_g1 * (H_ * DV_) + h * DV_ + cl]) =
            __floats2half2_rn(Oacc[nt][2] * inv1, Oacc[nt][3] * inv1);
    }
}

// ------------------------------ prep kernels --------------------------------
__global__ void convert4_kernel(const float* s0, __half* d0, long c0,
                                const float* s1, __half* d1, long c1,
                                const float* s2, __half* d2, long c2,
                                const float* s3, __half* d3, long c3)
{
    long i = (long)blockIdx.x * blockDim.x + threadIdx.x;
    const float* s; __half* d;
    if (i < c0)                { s = s0; d = d0; }
    else if ((i -= c0) < c1)   { s = s1; d = d1; }
    else if ((i -= c1) < c2)   { s = s2; d = d2; }
    else if ((i -= c2) < c3)   { s = s3; d = d3; }
    else return;
    long e = i * 4;
    float4 v = *reinterpret_cast<const float4*>(s + e);
    union { __half2 h[2]; uint2 u; } cv;
    cv.h[0] = __floats2half2_rn(v.x, v.y);
    cv.h[1] = __floats2half2_rn(v.z, v.w);
    *reinterpret_cast<uint2*>(d + e) = cv.u;
}

__global__ void tohalf8_strided(const float* __restrict__ in, int ldin, int Cin,
                                __half* __restrict__ out, int ldout, int chunks)
{
    long idx = (long)blockIdx.x * blockDim.x + threadIdx.x;
    int r  = (int)(idx / chunks);
    int c  = (int)(idx % chunks) * 8;
    union { __half2 h[4]; uint4 u; } cv;
    if (c < Cin) {
        const float* src = in + (long)r * ldin + c;
        float4 a = *reinterpret_cast<const float4*>(src);
        float4 b = *reinterpret_cast<const float4*>(src + 4);
        cv.h[0] = __floats2half2_rn(a.x, a.y);
        cv.h[1] = __floats2half2_rn(a.z, a.w);
        cv.h[2] = __floats2half2_rn(b.x, b.y);
        cv.h[3] = __floats2half2_rn(b.z, b.w);
    } else {
        cv.u = make_uint4(0, 0, 0, 0);
    }
    *reinterpret_cast<uint4*>(out + (long)r * ldout + c) = cv.u;
}

// ------------------------------ RMSNorm (half out) --------------------------
__global__ void rmsnorm_h_kernel(const float* __restrict__ x,
                                 const float* __restrict__ w,
                                 __half* __restrict__ y,
                                 int L, int ldx, int ldy)
{
    const int row = blockIdx.x, tid = threadIdx.x;
    const float* xr = x + (long)row * ldx;
    __half* yr = y + (long)row * ldy;

    __shared__ float red[256];
    float s = 0.0f;
    for (int i = tid; i < L; i += 256) { float v = xr[i]; s += v * v; }
    red[tid] = s; __syncthreads();
    for (int o = 128; o > 0; o >>= 1) {
        if (tid < o) red[tid] += red[tid + o];
        __syncthreads();
    }
    const float scale = rsqrtf(red[0] / (float)L + EPS_);
    for (int i = tid; i < L; i += 256)
        yr[i] = __float2half_rn(xr[i] * scale * w[i]);
}

// -------------------------------- RoPE --------------------------------------
__global__ void rope_q_kernel(__half* __restrict__ q,
                              const float* __restrict__ cosT,
                              const float* __restrict__ sinT, int t0)
{
    const int t = t0 + blockIdx.x;
    const int w = threadIdx.x >> 5, lane = threadIdx.x & 31;
    const float c = cosT[(long)t * DR_ + lane];
    const float s = sinT[(long)t * DR_ + lane];
    #pragma unroll
    for (int it = 0; it < 4; it++) {
        int h = it * 8 + w;
        __half* p = q + (long)t * (H_ * DQK_) + h * DQK_ + DN_;
        __half2 v = *reinterpret_cast<const __half2*>(p + 2 * lane);
        float lo = __half2float(v.x), hi = __half2float(v.y);
        __syncwarp();
        p[lane]      = __float2half_rn(lo * c - hi * s);
        p[lane + 32] = __float2half_rn(hi * c + lo * s);
    }
}

__global__ void rope_k_kernel(const float* __restrict__ ckv_pe,
                              __half* __restrict__ kr,
                              const float* __restrict__ cosT,
                              const float* __restrict__ sinT, int ld)
{
    const int t = blockIdx.x * 8 + (threadIdx.x >> 5);
    const int lane = threadIdx.x & 31;
    const float c = cosT[(long)t * DR_ + lane];
    const float s = sinT[(long)t * DR_ + lane];
    float2 v = *reinterpret_cast<const float2*>(ckv_pe + (long)t * ld + 2 * lane);
    __half* o = kr + (long)t * DR_;
    o[lane]      = __float2half_rn(v.x * c - v.y * s);
    o[lane + 32] = __float2half_rn(v.y * c + v.x * s);
}

// ------------------------------- launch ------------------------------------
extern "C" void kernel_launch(void* const* d_in, const int* in_sizes, int n_in,
                              void* d_out, int out_size)
{
    const float* hidden = (const float*)d_in[0];
    const float* cosT   = (const float*)d_in[1];
    const float* sinT   = (const float*)d_in[2];
    const float* wq_a   = (const float*)d_in[3];
    const float* q_ln   = (const float*)d_in[4];
    const float* wq_b   = (const float*)d_in[5];
    const float* wkv_a  = (const float*)d_in[6];
    const float* kv_ln  = (const float*)d_in[7];
    const float* wkv_b  = (const float*)d_in[8];
    const float* wo     = (const float*)d_in[9];
    float* out = (float*)d_out;

    static __half *hidH = nullptr, *qa16 = nullptr, *q16 = nullptr,
                  *cn16 = nullptr, *kv16 = nullptr, *kr16 = nullptr,
                  *ctx16 = nullptr, *wqac = nullptr, *wqb = nullptr,
                  *wkvb = nullptr, *woH = nullptr;
    static float *qack = nullptr;
    static cudaStream_t s2 = nullptr;
    static cudaEvent_t evFork, evQA, evW, evA, evB, evQN, evAttnB;
    if (!qack) {
        cudaGetSymbolAddress((void**)&hidH,  g_hidH);
        cudaGetSymbolAddress((void**)&qack,  g_qack);
        cudaGetSymbolAddress((void**)&qa16,  g_qa16);
        cudaGetSymbolAddress((void**)&q16,   g_q16);
        cudaGetSymbolAddress((void**)&cn16,  g_cn16);
        cudaGetSymbolAddress((void**)&kv16,  g_kv16);
        cudaGetSymbolAddress((void**)&kr16,  g_kr16);
        cudaGetSymbolAddress((void**)&ctx16, g_ctx16);
        cudaGetSymbolAddress((void**)&wqac,  g_wqac);
        cudaGetSymbolAddress((void**)&wqb,   g_wqb);
        cudaGetSymbolAddress((void**)&wkvb,  g_wkvb);
        cudaGetSymbolAddress((void**)&woH,   g_wo);
        cudaFuncSetAttribute(hgemm_kernel<0>,
                             cudaFuncAttributeMaxDynamicSharedMemorySize, GSMEM_BYTES);
        cudaFuncSetAttribute(hgemm_kernel<1>,
                             cudaFuncAttributeMaxDynamicSharedMemorySize, GSMEM_BYTES);
        cudaFuncSetAttribute(fused_attn_kernel,
                             cudaFuncAttributeMaxDynamicSharedMemorySize, FUSED_SMEM);
        cudaStreamCreateWithFlags(&s2, cudaStreamNonBlocking);
        cudaEventCreateWithFlags(&evFork, cudaEventDisableTiming);
        cudaEventCreateWithFlags(&evQA,   cudaEventDisableTiming);
        cudaEventCreateWithFlags(&evW,    cudaEventDisableTiming);
        cudaEventCreateWithFlags(&evA,    cudaEventDisableTiming);
        cudaEventCreateWithFlags(&evB,    cudaEventDisableTiming);
        cudaEventCreateWithFlags(&evQN,   cudaEventDisableTiming);
        cudaEventCreateWithFlags(&evAttnB, cudaEventDisableTiming);
    }

    const dim3 blk(256);
    const long ROWH = 1024;                        // split point (rows)

    // ---- fork second stream
    cudaEventRecord(evFork, 0);
    cudaStreamWaitEvent(s2, evFork, 0);

    // s2: merged A-proj weights first, then B/O weights
    tohalf8_strided<<<(HIDDEN_ * (QL_ / 8)) / 256, 256, 0, s2>>>(
        wq_a, QL_, QL_, wqac, NMERGE_, QL_ / 8);
    tohalf8_strided<<<(HIDDEN_ * (CKVP_ / 8)) / 256, 256, 0, s2>>>(
        wkv_a, KVL_ + DR_, KVL_ + DR_, wqac + QL_, NMERGE_, CKVP_ / 8);
    cudaEventRecord(evQA, s2);
    const long c1 = (long)QL_ * (H_ * DQK_) / 4;
    const long c2 = (long)KVL_ * (H_ * (DN_ + DV_)) / 4;
    const long c3 = (long)(H_ * DV_) * HIDDEN_ / 4;
    convert4_kernel<<<(int)((c1 + c2 + c3 + 255) / 256), 256, 0, s2>>>(
        wq_b, wqb, c1, wkv_b, wkvb, c2, wo, woH, c3, nullptr, nullptr, 0);
    cudaEventRecord(evW, s2);

    // s0: hidden convert
    const long c0 = (long)T_ * HIDDEN_ / 4;
    convert4_kernel<<<(int)((c0 + 255) / 256), 256>>>(
        hidden, hidH, c0, nullptr, nullptr, 0, nullptr, nullptr, 0,
        nullptr, nullptr, 0);

    // merged GEMM (needs hidH + wqac)
    cudaStreamWaitEvent(0, evQA, 0);
    hgemm_kernel<0><<<dim3(NMERGE_ / 128, 16), blk, GSMEM_BYTES>>>(
        hidH, wqac, qack, T_, NMERGE_, HIDDEN_, HIDDEN_, NMERGE_, NMERGE_);
    cudaEventRecord(evA, 0);

    // kv chain on s2
    cudaStreamWaitEvent(s2, evA, 0);
    rmsnorm_h_kernel<<<T_, 256, 0, s2>>>(qack + QL_, kv_ln, cn16, KVL_, NMERGE_, KVL_);
    hgemm_kernel<1><<<dim3(H_ * (DN_ + DV_) / 128, 16), blk, GSMEM_BYTES, s2>>>(
        cn16, wkvb, kv16, T_, H_ * (DN_ + DV_), KVL_,
        KVL_, H_ * (DN_ + DV_), H_ * (DN_ + DV_));
    rope_k_kernel<<<T_ / 8, 256, 0, s2>>>(qack + QL_ + KVL_, kr16, cosT, sinT, NMERGE_);
    cudaEventRecord(evB, s2);

    // q-norm on main (full), then split GEMM3 into row halves
    rmsnorm_h_kernel<<<T_, 256>>>(qack, q_ln, qa16, QL_, NMERGE_, QL_);
    cudaEventRecord(evQN, 0);
    cudaStreamWaitEvent(0, evW, 0);

    // --- main: TOP half (rows 1024-2047): GEMM3_A -> rope_qA -> attn_A
    hgemm_kernel<1><<<dim3(H_ * DQK_ / 128, 8), blk, GSMEM_BYTES>>>(
        qa16 + ROWH * QL_, wqb, q16 + ROWH * (H_ * DQK_),
        (int)ROWH, H_ * DQK_, QL_, QL_, H_ * DQK_, H_ * DQK_);
    rope_q_kernel<<<1024, 256>>>(q16, cosT, sinT, 1024);
    cudaStreamWaitEvent(0, evB, 0);
    fused_attn_kernel<<<dim3(16, H_), 128, FUSED_SMEM>>>(
        q16, kv16, kr16, ctx16, 31);

    // --- s2: BOTTOM half (rows 0-1023): GEMM3_B -> rope_qB -> attn_B
    cudaStreamWaitEvent(s2, evQN, 0);
    hgemm_kernel<1><<<dim3(H_ * DQK_ / 128, 8), blk, GSMEM_BYTES, s2>>>(
        qa16, wqb, q16, (int)ROWH, H_ * DQK_, QL_, QL_, H_ * DQK_, H_ * DQK_);
    rope_q_kernel<<<1024, 256, 0, s2>>>(q16, cosT, sinT, 0);
    fused_attn_kernel<<<dim3(16, H_), 128, FUSED_SMEM, s2>>>(
        q16, kv16, kr16, ctx16, 15);
    cudaEventRecord(evAttnB, s2);

    // --- out GEMM: top half after attn_A, bottom after attn_B join
    hgemm_kernel<0><<<dim3(HIDDEN_ / 128, 8), blk, GSMEM_BYTES>>>(
        ctx16 + ROWH * (H_ * DV_), woH, out + ROWH * HIDDEN_,
        (int)ROWH, HIDDEN_, H_ * DV_, H_ * DV_, HIDDEN_, HIDDEN_);
    cudaStreamWaitEvent(0, evAttnB, 0);
    hgemm_kernel<0><<<dim3(HIDDEN_ / 128, 8), blk, GSMEM_BYTES>>>(
        ctx16, woH, out, (int)ROWH, HIDDEN_, H_ * DV_, H_ * DV_, HIDDEN_, HIDDEN_);
}